// round 1
// baseline (speedup 1.0000x reference)
#include <cuda_runtime.h>

#define NIMG 800

// ---------------- scratch (no allocation allowed) ----------------
__device__ float  g_buf1[NIMG * 4 * 30 * 30];   // conv1 pooled output (NCHW)
__device__ float  g_buf2[NIMG * 8 * 25];        // conv2 pooled output (NCHW)
__device__ float  g_z[NIMG * 2];
__device__ float  g_L[NIMG * 3];
__device__ double g_stats[24];  // [0:4) bn1 sum, [4:8) bn1 sumsq, [8:16) bn2 sum, [16:24) bn2 sumsq

__global__ void k_init() {
    if (threadIdx.x < 24) g_stats[threadIdx.x] = 0.0;
}

// ---------------- conv1 + bias + relu + maxpool2 + bn1-stats ----------------
// input x: (N,128,128,3) NHWC interleaved. conv 9x9 stride 2 -> 60x60, pool -> 30x30.
// Block: one image, 5 pooled rows (tile). Thread: one pooled pixel, all 4 oc.
__global__ __launch_bounds__(160) void k_conv1(
    const float* __restrict__ x, const float* __restrict__ cw,
    const float* __restrict__ cb)
{
    __shared__ __align__(16) float sm_in[3 * 3460];  // planar [3][27][128], plane stride 3460 (pad vs bank conflicts)
    __shared__ __align__(16) float sm_w[972];        // [ic][kh][kw][oc]
    __shared__ float sm_b[4];
    __shared__ float s_sum[4], s_sq[4];
    const int tid = threadIdx.x;
    const int n   = blockIdx.y;
    const int r0  = blockIdx.x * 5;   // first pooled row of tile

    if (tid < 4) { s_sum[tid] = 0.f; s_sq[tid] = 0.f; sm_b[tid] = cb[tid]; }
    // weights: global OIHW (4,3,9,9) -> smem [((ic*9+kh)*9+kw)*4 + oc]
    for (int i = tid; i < 972; i += 160) {
        int oc = i & 3; int rest = i >> 2;
        int kw = rest % 9; int t2 = rest / 9; int kh = t2 % 9; int ic = t2 / 9;
        sm_w[i] = cw[oc * 243 + ic * 81 + kh * 9 + kw];
    }
    // input rows 4*r0 .. 4*r0+26 (27 rows), de-interleave NHWC -> planar
    const float* xb = x + (size_t)n * 49152 + (size_t)r0 * 4 * 384;
    for (int i = tid; i < 27 * 384; i += 160) {
        int row = i / 384; int rem = i - row * 384;
        int wc = rem / 3;  int ch = rem - wc * 3;
        sm_in[ch * 3460 + row * 128 + wc] = xb[i];
    }
    __syncthreads();

    if (tid < 150) {
        const int pw  = tid % 30;
        const int phl = tid / 30;
        float acc[4][2][2];
        #pragma unroll
        for (int a = 0; a < 4; a++)
            #pragma unroll
            for (int b = 0; b < 2; b++) { acc[a][b][0] = 0.f; acc[a][b][1] = 0.f; }

        #pragma unroll 1
        for (int ic = 0; ic < 3; ic++) {
            const float* pl = sm_in + ic * 3460 + phl * 512 + pw * 4;
            #pragma unroll
            for (int r = 0; r < 11; r++) {    // r = 2*dy + kh  (local input row)
                float4 va = *(const float4*)(pl + r * 128);
                float4 vb = *(const float4*)(pl + r * 128 + 4);
                float4 vc = *(const float4*)(pl + r * 128 + 8);
                float inr[12] = {va.x, va.y, va.z, va.w, vb.x, vb.y, vb.z, vb.w,
                                 vc.x, vc.y, vc.z, vc.w};
                #pragma unroll
                for (int dy = 0; dy < 2; dy++) {
                    const int kh = r - 2 * dy;
                    if (kh < 0 || kh > 8) continue;
                    #pragma unroll
                    for (int kw = 0; kw < 9; kw++) {
                        float4 w4 = *(const float4*)(sm_w + ((ic * 9 + kh) * 9 + kw) * 4);
                        #pragma unroll
                        for (int dx = 0; dx < 2; dx++) {
                            const float iv = inr[2 * dx + kw];
                            acc[0][dy][dx] = fmaf(w4.x, iv, acc[0][dy][dx]);
                            acc[1][dy][dx] = fmaf(w4.y, iv, acc[1][dy][dx]);
                            acc[2][dy][dx] = fmaf(w4.z, iv, acc[2][dy][dx]);
                            acc[3][dy][dx] = fmaf(w4.w, iv, acc[3][dy][dx]);
                        }
                    }
                }
            }
        }
        const int ph = r0 + phl;
        #pragma unroll
        for (int oc = 0; oc < 4; oc++) {
            float b = sm_b[oc];
            float m = fmaxf(fmaxf(acc[oc][0][0], acc[oc][0][1]),
                            fmaxf(acc[oc][1][0], acc[oc][1][1]));
            m = fmaxf(m + b, 0.f);   // relu(max+b) == max(relu(..)) for shared bias
            g_buf1[((n * 4 + oc) * 30 + ph) * 30 + pw] = m;
            atomicAdd(&s_sum[oc], m);
            atomicAdd(&s_sq[oc], m * m);
        }
    }
    __syncthreads();
    if (tid < 4) {
        atomicAdd(&g_stats[tid],     (double)s_sum[tid]);
        atomicAdd(&g_stats[4 + tid], (double)s_sq[tid]);
    }
}

// ---------------- bn1-apply + conv2 + relu + pool + bn2-stats ----------------
// in (N,4,30,30) -> conv 9x9 s2 -> 11x11 -> pool(VALID) -> 5x5, 8 oc.
__global__ __launch_bounds__(256) void k_conv2(
    const float* __restrict__ cw, const float* __restrict__ cb,
    const float* __restrict__ g1, const float* __restrict__ b1)
{
    __shared__ float sm_in[3600];
    __shared__ float sm_w[2592];
    __shared__ float sm_b[8];
    __shared__ float sc[4], shh[4];
    __shared__ float s_sum[8], s_sq[8];
    const int tid = threadIdx.x;
    const int n   = blockIdx.x;
    if (tid < 4) {
        double mu  = g_stats[tid] * (1.0 / 720000.0);
        double var = g_stats[4 + tid] * (1.0 / 720000.0) - mu * mu;
        float scale = g1[tid] * rsqrtf((float)var + 1e-5f);
        sc[tid] = scale; shh[tid] = b1[tid] - (float)mu * scale;
    }
    if (tid < 8) { s_sum[tid] = 0.f; s_sq[tid] = 0.f; sm_b[tid] = cb[tid]; }
    __syncthreads();
    for (int i = tid; i < 3600; i += 256) {
        int ch = i / 900;
        sm_in[i] = fmaf(g_buf1[n * 3600 + i], sc[ch], shh[ch]);
    }
    for (int i = tid; i < 2592; i += 256) sm_w[i] = cw[i];
    __syncthreads();
    if (tid < 200) {
        const int oc = tid / 25;
        const int p  = tid % 25;
        const int pr = p / 5, pc = p % 5;
        float acc[2][2] = {{0.f, 0.f}, {0.f, 0.f}};
        #pragma unroll 1
        for (int ic = 0; ic < 4; ic++) {
            const float* wp = sm_w + oc * 324 + ic * 81;
            const float* ip = sm_in + ic * 900 + pr * 120 + pc * 4;
            #pragma unroll
            for (int kh = 0; kh < 9; kh++) {
                #pragma unroll
                for (int kw = 0; kw < 9; kw++) {
                    float wv = wp[kh * 9 + kw];
                    #pragma unroll
                    for (int dy = 0; dy < 2; dy++)
                        #pragma unroll
                        for (int dx = 0; dx < 2; dx++)
                            acc[dy][dx] = fmaf(wv, ip[(2 * dy + kh) * 30 + 2 * dx + kw], acc[dy][dx]);
                }
            }
        }
        float b = sm_b[oc];
        float m = fmaxf(fmaxf(acc[0][0], acc[0][1]), fmaxf(acc[1][0], acc[1][1]));
        m = fmaxf(m + b, 0.f);
        g_buf2[(n * 8 + oc) * 25 + p] = m;
        atomicAdd(&s_sum[oc], m);
        atomicAdd(&s_sq[oc], m * m);
    }
    __syncthreads();
    if (tid < 8) {
        atomicAdd(&g_stats[8 + tid],  (double)s_sum[tid]);
        atomicAdd(&g_stats[16 + tid], (double)s_sq[tid]);
    }
}

// ---------------- bn2-apply + fc1(relu) + fc2(relu) + fc3z / fc3L ----------------
__global__ __launch_bounds__(128) void k_fc(
    const float* __restrict__ W1, const float* __restrict__ b1,
    const float* __restrict__ W2, const float* __restrict__ b2,
    const float* __restrict__ Wz, const float* __restrict__ bz,
    const float* __restrict__ WL, const float* __restrict__ bL,
    const float* __restrict__ g2, const float* __restrict__ be2)
{
    __shared__ float sW1[3200], sW2[512], sWz[64], sWL[96];
    __shared__ float sb1[16], sb2[32], sbz[2], sbL[3];
    __shared__ float sc[8], shh[8];
    const int tid = threadIdx.x;
    if (tid < 8) {
        double mu  = g_stats[8 + tid] * (1.0 / 20000.0);
        double var = g_stats[16 + tid] * (1.0 / 20000.0) - mu * mu;
        float scale = g2[tid] * rsqrtf((float)var + 1e-5f);
        sc[tid] = scale; shh[tid] = be2[tid] - (float)mu * scale;
    }
    for (int i = tid; i < 3200; i += 128) sW1[i] = W1[i];
    for (int i = tid; i < 512;  i += 128) sW2[i] = W2[i];
    if (tid < 64) sWz[tid] = Wz[tid];
    if (tid < 96) sWL[tid] = WL[tid];
    if (tid < 16) sb1[tid] = b1[tid];
    if (tid < 32) sb2[tid] = b2[tid];
    if (tid < 2)  sbz[tid] = bz[tid];
    if (tid < 3)  sbL[tid] = bL[tid];
    __syncthreads();
    const int n = blockIdx.x * 128 + tid;
    if (n >= NIMG) return;

    float f1[16];
    #pragma unroll
    for (int i = 0; i < 16; i++) f1[i] = sb1[i];
    const float* src = g_buf2 + n * 200;
    for (int j = 0; j < 200; j++) {
        int ch = j / 25;
        float fv = fmaf(src[j], sc[ch], shh[ch]);
        #pragma unroll
        for (int i = 0; i < 16; i++) f1[i] = fmaf(sW1[i * 200 + j], fv, f1[i]);
    }
    #pragma unroll
    for (int i = 0; i < 16; i++) f1[i] = fmaxf(f1[i], 0.f);
    float f2[32];
    #pragma unroll
    for (int i = 0; i < 32; i++) {
        float a = sb2[i];
        #pragma unroll
        for (int j = 0; j < 16; j++) a = fmaf(sW2[i * 16 + j], f1[j], a);
        f2[i] = fmaxf(a, 0.f);
    }
    float z0 = sbz[0], z1 = sbz[1];
    float L0 = sbL[0], L1 = sbL[1], L2 = sbL[2];
    #pragma unroll
    for (int j = 0; j < 32; j++) {
        z0 = fmaf(sWz[j],      f2[j], z0);
        z1 = fmaf(sWz[32 + j], f2[j], z1);
        L0 = fmaf(sWL[j],      f2[j], L0);
        L1 = fmaf(sWL[32 + j], f2[j], L1);
        L2 = fmaf(sWL[64 + j], f2[j], L2);
    }
    g_z[n * 2] = z0;  g_z[n * 2 + 1] = z1;
    g_L[n * 3] = L0;  g_L[n * 3 + 1] = L1;  g_L[n * 3 + 2] = L2;
}

// ---------------- Kalman filter: one lane per sequence (8 lanes, 1 warp) ----------------
__global__ void k_kf(const float* __restrict__ Ag, const float* __restrict__ Bg,
                     const float* __restrict__ Cg, const float* __restrict__ Qg,
                     float* __restrict__ out)
{
    const int b = threadIdx.x;
    if (b >= 8) return;
    float A[16], C[8], BQBT[16], Bm[8], Q[4];
    #pragma unroll
    for (int i = 0; i < 16; i++) A[i] = Ag[i];
    #pragma unroll
    for (int i = 0; i < 8; i++)  C[i] = Cg[i];
    #pragma unroll
    for (int i = 0; i < 8; i++)  Bm[i] = Bg[i];
    #pragma unroll
    for (int i = 0; i < 4; i++)  Q[i] = Qg[i];
    #pragma unroll
    for (int i = 0; i < 4; i++) {
        float bq0 = Bm[i * 2] * Q[0] + Bm[i * 2 + 1] * Q[2];
        float bq1 = Bm[i * 2] * Q[1] + Bm[i * 2 + 1] * Q[3];
        #pragma unroll
        for (int l = 0; l < 4; l++)
            BQBT[i * 4 + l] = bq0 * Bm[l * 2] + bq1 * Bm[l * 2 + 1];
    }
    const float* zp = g_z + b * 200;
    const float* Lp = g_L + b * 300;
    float h[4] = {zp[0], zp[1], 0.f, 0.f};
    {
        float l0 = Lp[0], l1 = Lp[1];
    }
    float l0 = Lp[0], l1 = Lp[1], l2 = Lp[2];
    float s[16] = {l0 * l0, l0 * l1, 0.f, 0.f,
                   l0 * l1, l1 * l1 + l2 * l2, 0.f, 0.f,
                   0.f, 0.f, 1.f, 0.f,
                   0.f, 0.f, 0.f, 1.f};
    float* ob = out + b * 400;
    ob[0] = h[0]; ob[1] = h[1]; ob[2] = h[2]; ob[3] = h[3];

    for (int t = 1; t < 100; t++) {
        float zx = zp[t * 2], zy = zp[t * 2 + 1];
        float La = Lp[t * 3], Lb = Lp[t * 3 + 1], Lc = Lp[t * 3 + 2];
        float r00 = La * La, r01 = La * Lb, r11 = Lb * Lb + Lc * Lc;
        float hp[4];
        #pragma unroll
        for (int i = 0; i < 4; i++)
            hp[i] = A[i*4]*h[0] + A[i*4+1]*h[1] + A[i*4+2]*h[2] + A[i*4+3]*h[3];
        float tmp[16];
        #pragma unroll
        for (int i = 0; i < 4; i++)
            #pragma unroll
            for (int k = 0; k < 4; k++)
                tmp[i*4+k] = A[i*4]*s[k] + A[i*4+1]*s[4+k] + A[i*4+2]*s[8+k] + A[i*4+3]*s[12+k];
        float sp[16];
        #pragma unroll
        for (int i = 0; i < 4; i++)
            #pragma unroll
            for (int l = 0; l < 4; l++)
                sp[i*4+l] = BQBT[i*4+l] + tmp[i*4]*A[l*4] + tmp[i*4+1]*A[l*4+1]
                          + tmp[i*4+2]*A[l*4+2] + tmp[i*4+3]*A[l*4+3];
        float sct[8];  // sp @ C^T  (4x2)
        #pragma unroll
        for (int i = 0; i < 4; i++)
            #pragma unroll
            for (int j = 0; j < 2; j++)
                sct[i*2+j] = sp[i*4]*C[j*4] + sp[i*4+1]*C[j*4+1]
                           + sp[i*4+2]*C[j*4+2] + sp[i*4+3]*C[j*4+3];
        float S00 = C[0]*sct[0] + C[1]*sct[2] + C[2]*sct[4] + C[3]*sct[6] + r00;
        float S01 = C[0]*sct[1] + C[1]*sct[3] + C[2]*sct[5] + C[3]*sct[7] + r01;
        float S10 = C[4]*sct[0] + C[5]*sct[2] + C[6]*sct[4] + C[7]*sct[6] + r01;
        float S11 = C[4]*sct[1] + C[5]*sct[3] + C[6]*sct[5] + C[7]*sct[7] + r11;
        float idet = 1.f / (S00 * S11 - S01 * S10);
        float Si00 = S11 * idet, Si01 = -S01 * idet, Si10 = -S10 * idet, Si11 = S00 * idet;
        float K[8];
        #pragma unroll
        for (int i = 0; i < 4; i++) {
            K[i*2]   = sct[i*2]*Si00 + sct[i*2+1]*Si10;
            K[i*2+1] = sct[i*2]*Si01 + sct[i*2+1]*Si11;
        }
        float a0 = zx - (C[0]*hp[0] + C[1]*hp[1] + C[2]*hp[2] + C[3]*hp[3]);
        float a1 = zy - (C[4]*hp[0] + C[5]*hp[1] + C[6]*hp[2] + C[7]*hp[3]);
        #pragma unroll
        for (int i = 0; i < 4; i++) h[i] = hp[i] + K[i*2]*a0 + K[i*2+1]*a1;
        float M[16];
        #pragma unroll
        for (int i = 0; i < 4; i++)
            #pragma unroll
            for (int j = 0; j < 4; j++)
                M[i*4+j] = (i == j ? 1.f : 0.f) - (K[i*2]*C[j] + K[i*2+1]*C[4+j]);
        #pragma unroll
        for (int i = 0; i < 4; i++)
            #pragma unroll
            for (int l = 0; l < 4; l++)
                s[i*4+l] = M[i*4]*sp[l] + M[i*4+1]*sp[4+l]
                         + M[i*4+2]*sp[8+l] + M[i*4+3]*sp[12+l];
        ob[t*4]   = h[0]; ob[t*4+1] = h[1];
        ob[t*4+2] = h[2]; ob[t*4+3] = h[3];
    }
}

extern "C" void kernel_launch(void* const* d_in, const int* in_sizes, int n_in,
                              void* d_out, int out_size) {
    const float* x    = (const float*)d_in[0];
    const float* c1w  = (const float*)d_in[1];
    const float* c1b  = (const float*)d_in[2];
    const float* bn1g = (const float*)d_in[3];
    const float* bn1b = (const float*)d_in[4];
    const float* c2w  = (const float*)d_in[5];
    const float* c2b  = (const float*)d_in[6];
    const float* bn2g = (const float*)d_in[7];
    const float* bn2b = (const float*)d_in[8];
    const float* W1   = (const float*)d_in[9];
    const float* b1   = (const float*)d_in[10];
    const float* W2   = (const float*)d_in[11];
    const float* b2   = (const float*)d_in[12];
    const float* Wz   = (const float*)d_in[13];
    const float* bz   = (const float*)d_in[14];
    const float* WL   = (const float*)d_in[15];
    const float* bL   = (const float*)d_in[16];
    const float* A    = (const float*)d_in[17];
    const float* B    = (const float*)d_in[18];
    const float* C    = (const float*)d_in[19];
    const float* Q    = (const float*)d_in[20];
    float* out = (float*)d_out;

    k_init<<<1, 32>>>();
    k_conv1<<<dim3(6, 800), 160>>>(x, c1w, c1b);
    k_conv2<<<800, 256>>>(c2w, c2b, bn1g, bn1b);
    k_fc<<<7, 128>>>(W1, b1, W2, b2, Wz, bz, WL, bL, bn2g, bn2b);
    k_kf<<<1, 32>>>(A, B, C, Q, out);
}

// round 2
// speedup vs baseline: 1.6825x; 1.6825x over previous
#include <cuda_runtime.h>

#define NIMG 800

// ---------------- scratch (no allocation allowed) ----------------
__device__ float  g_buf1[NIMG * 4 * 30 * 30];   // conv1 pooled output (NCHW)
__device__ float  g_buf2[NIMG * 8 * 25];        // conv2 pooled output (NCHW)
__device__ float  g_z[NIMG * 2];
__device__ float  g_L[NIMG * 3];
__device__ double g_stats[24];  // [0:4) bn1 sum, [4:8) bn1 sumsq, [8:16) bn2 sum, [16:24) bn2 sumsq
__device__ int    g_sink;

__global__ void k_zero() { if (threadIdx.x < 24) g_stats[threadIdx.x] = 0.0; }
__global__ void k_pad1() { if (threadIdx.x == 0) g_sink = 1; }
__global__ void k_pad2() { if (threadIdx.x == 0) g_sink = 2; }

// ---------------- conv1 + bias + relu + maxpool2 + bn1-stats ----------------
// input x: (N,128,128,3) NHWC. conv 9x9 stride 2 -> 60x60, pool -> 30x30.
// Block: one image, 5 pooled rows. Thread: one pooled pixel, all 4 oc.
__global__ __launch_bounds__(160) void k_conv1(
    const float* __restrict__ x, const float* __restrict__ cw,
    const float* __restrict__ cb)
{
    __shared__ __align__(16) float sm_in[3 * 3460];  // planar [3][27][128], plane stride 3460
    __shared__ __align__(16) float sm_w[972];        // [ic][kh][kw][oc]
    __shared__ float sm_b[4];
    __shared__ float s_part[5][8];
    const int tid = threadIdx.x;
    const int n   = blockIdx.y;
    const int r0  = blockIdx.x * 5;

    if (tid < 4) sm_b[tid] = cb[tid];
    // weights: global OIHW (4,3,9,9) -> smem [((ic*9+kh)*9+kw)*4 + oc]
    for (int i = tid; i < 972; i += 160) {
        int oc = i & 3; int rest = i >> 2;
        int kw = rest % 9; int t2 = rest / 9; int kh = t2 % 9; int ic = t2 / 9;
        sm_w[i] = cw[oc * 243 + ic * 81 + kh * 9 + kw];
    }
    // input rows 4*r0 .. 4*r0+26 (27 rows), de-interleave NHWC -> planar
    const float* xb = x + (size_t)n * 49152 + (size_t)r0 * 4 * 384;
    for (int i = tid; i < 27 * 384; i += 160) {
        int row = i / 384; int rem = i - row * 384;
        int wc = rem / 3;  int ch = rem - wc * 3;
        sm_in[ch * 3460 + row * 128 + wc] = xb[i];
    }
    __syncthreads();

    const bool valid = (tid < 150);
    const int pw  = tid % 30;
    const int phl = valid ? (tid / 30) : 4;
    float acc[4][2][2];
    #pragma unroll
    for (int a = 0; a < 4; a++)
        #pragma unroll
        for (int b = 0; b < 2; b++) { acc[a][b][0] = 0.f; acc[a][b][1] = 0.f; }

    #pragma unroll 1
    for (int ic = 0; ic < 3; ic++) {
        const float* pl = sm_in + ic * 3460 + phl * 512 + pw * 4;
        #pragma unroll
        for (int r = 0; r < 11; r++) {
            float4 va = *(const float4*)(pl + r * 128);
            float4 vb = *(const float4*)(pl + r * 128 + 4);
            float4 vc = *(const float4*)(pl + r * 128 + 8);
            float inr[12] = {va.x, va.y, va.z, va.w, vb.x, vb.y, vb.z, vb.w,
                             vc.x, vc.y, vc.z, vc.w};
            #pragma unroll
            for (int dy = 0; dy < 2; dy++) {
                const int kh = r - 2 * dy;
                if (kh < 0 || kh > 8) continue;
                #pragma unroll
                for (int kw = 0; kw < 9; kw++) {
                    float4 w4 = *(const float4*)(sm_w + ((ic * 9 + kh) * 9 + kw) * 4);
                    #pragma unroll
                    for (int dx = 0; dx < 2; dx++) {
                        const float iv = inr[2 * dx + kw];
                        acc[0][dy][dx] = fmaf(w4.x, iv, acc[0][dy][dx]);
                        acc[1][dy][dx] = fmaf(w4.y, iv, acc[1][dy][dx]);
                        acc[2][dy][dx] = fmaf(w4.z, iv, acc[2][dy][dx]);
                        acc[3][dy][dx] = fmaf(w4.w, iv, acc[3][dy][dx]);
                    }
                }
            }
        }
    }
    const int ph = r0 + phl;
    float vs[4], vq[4];
    #pragma unroll
    for (int oc = 0; oc < 4; oc++) {
        float b = sm_b[oc];
        float m = fmaxf(fmaxf(acc[oc][0][0], acc[oc][0][1]),
                        fmaxf(acc[oc][1][0], acc[oc][1][1]));
        m = fmaxf(m + b, 0.f);
        if (valid) g_buf1[((n * 4 + oc) * 30 + ph) * 30 + pw] = m;
        vs[oc] = valid ? m : 0.f;
        vq[oc] = valid ? m * m : 0.f;
    }
    #pragma unroll
    for (int oc = 0; oc < 4; oc++)
        #pragma unroll
        for (int off = 16; off > 0; off >>= 1) {
            vs[oc] += __shfl_xor_sync(0xffffffffu, vs[oc], off);
            vq[oc] += __shfl_xor_sync(0xffffffffu, vq[oc], off);
        }
    const int wp = tid >> 5;
    if ((tid & 31) == 0) {
        #pragma unroll
        for (int oc = 0; oc < 4; oc++) {
            s_part[wp][oc]     = vs[oc];
            s_part[wp][4 + oc] = vq[oc];
        }
    }
    __syncthreads();
    if (tid < 8) {
        float t = 0.f;
        #pragma unroll
        for (int w = 0; w < 5; w++) t += s_part[w][tid];
        atomicAdd(&g_stats[tid], (double)t);
    }
}

// ---------------- bn1-apply + conv2 + relu + pool + bn2-stats ----------------
// in (N,4,30,30) -> conv 9x9 s2 -> 11x11 -> pool(VALID) -> 5x5, 8 oc.
// smem input layout: [ic][row][32] with 16B-chunk XOR swizzle by (row&7).
__global__ __launch_bounds__(224) void k_conv2(
    const float* __restrict__ cw, const float* __restrict__ cb,
    const float* __restrict__ g1, const float* __restrict__ b1)
{
    __shared__ __align__(16) float sm_in[4 * 960];
    __shared__ float sm_w[2592];
    __shared__ float sm_b[8];
    __shared__ float sc[4], shh[4];
    __shared__ float s_sum[8], s_sq[8];
    const int tid = threadIdx.x;
    const int n   = blockIdx.x;
    if (tid < 4) {
        double mu  = g_stats[tid] * (1.0 / 720000.0);
        double var = g_stats[4 + tid] * (1.0 / 720000.0) - mu * mu;
        float scale = g1[tid] * rsqrtf((float)var + 1e-5f);
        sc[tid] = scale; shh[tid] = b1[tid] - (float)mu * scale;
    }
    if (tid < 8) { s_sum[tid] = 0.f; s_sq[tid] = 0.f; sm_b[tid] = cb[tid]; }
    __syncthreads();
    for (int i = tid; i < 3600; i += 224) {
        int ic = i / 900; int rem = i - ic * 900;
        int row = rem / 30; int col = rem - row * 30;
        int chunk = col >> 2, within = col & 3;
        int pcol = (((chunk ^ (row & 7)) << 2) | within);
        sm_in[ic * 960 + row * 32 + pcol] = fmaf(g_buf1[n * 3600 + i], sc[ic], shh[ic]);
    }
    for (int i = tid; i < 2592; i += 224) sm_w[i] = cw[i];
    __syncthreads();
    if (tid < 200) {
        const int oc = tid / 25;
        const int p  = tid - oc * 25;
        const int pr = p / 5, pc = p - pr * 5;
        float acc[2][2] = {{0.f, 0.f}, {0.f, 0.f}};
        #pragma unroll 1
        for (int ic = 0; ic < 4; ic++) {
            const float* wb = sm_w + oc * 324 + ic * 81;
            const float* ib = sm_in + ic * 960;
            #pragma unroll 1
            for (int kh = 0; kh < 9; kh++) {
                float w[9];
                #pragma unroll
                for (int kw = 0; kw < 9; kw++) w[kw] = wb[kh * 9 + kw];
                #pragma unroll
                for (int dy = 0; dy < 2; dy++) {
                    const int row = 4 * pr + 2 * dy + kh;
                    const int rb  = row * 32;
                    const int rx  = row & 7;
                    float4 v0 = *(const float4*)(ib + rb + (((pc    ) ^ rx) << 2));
                    float4 v1 = *(const float4*)(ib + rb + (((pc + 1) ^ rx) << 2));
                    float4 v2 = *(const float4*)(ib + rb + (((pc + 2) ^ rx) << 2));
                    float in[12] = {v0.x, v0.y, v0.z, v0.w, v1.x, v1.y, v1.z, v1.w,
                                    v2.x, v2.y, v2.z, v2.w};
                    #pragma unroll
                    for (int kw = 0; kw < 9; kw++) {
                        acc[dy][0] = fmaf(w[kw], in[kw],     acc[dy][0]);
                        acc[dy][1] = fmaf(w[kw], in[kw + 2], acc[dy][1]);
                    }
                }
            }
        }
        float b = sm_b[oc];
        float m = fmaxf(fmaxf(acc[0][0], acc[0][1]), fmaxf(acc[1][0], acc[1][1]));
        m = fmaxf(m + b, 0.f);
        g_buf2[(n * 8 + oc) * 25 + p] = m;
        atomicAdd(&s_sum[oc], m);
        atomicAdd(&s_sq[oc], m * m);
    }
    __syncthreads();
    if (tid < 8) {
        atomicAdd(&g_stats[8 + tid],  (double)s_sum[tid]);
        atomicAdd(&g_stats[16 + tid], (double)s_sq[tid]);
    }
}

// ---------------- bn2-apply + fc1(relu) + fc2(relu) + fc3z / fc3L ----------------
// One warp per image; 100 blocks x 8 warps = 800 warps.
__global__ __launch_bounds__(256) void k_fc(
    const float* __restrict__ W1, const float* __restrict__ b1,
    const float* __restrict__ W2, const float* __restrict__ b2,
    const float* __restrict__ Wz, const float* __restrict__ bz,
    const float* __restrict__ WL, const float* __restrict__ bL,
    const float* __restrict__ g2, const float* __restrict__ be2)
{
    __shared__ float sW1[3200], sW2[512], sWz[64], sWL[96];
    __shared__ float sb1[16], sb2[32], sbz[2], sbL[3];
    __shared__ float sc[8], shh[8];
    const int tid = threadIdx.x;
    if (tid < 8) {
        double mu  = g_stats[8 + tid] * (1.0 / 20000.0);
        double var = g_stats[16 + tid] * (1.0 / 20000.0) - mu * mu;
        float scale = g2[tid] * rsqrtf((float)var + 1e-5f);
        sc[tid] = scale; shh[tid] = be2[tid] - (float)mu * scale;
    }
    for (int i = tid; i < 3200; i += 256) sW1[i] = W1[i];
    for (int i = tid; i < 512;  i += 256) sW2[i] = W2[i];
    if (tid < 64) sWz[tid] = Wz[tid];
    if (tid < 96) sWL[tid] = WL[tid];
    if (tid < 16) sb1[tid] = b1[tid];
    if (tid < 32) sb2[tid] = b2[tid];
    if (tid < 2)  sbz[tid] = bz[tid];
    if (tid < 3)  sbL[tid] = bL[tid];
    __syncthreads();

    const int lane = tid & 31;
    const int n = blockIdx.x * 8 + (tid >> 5);
    const float* src = g_buf2 + n * 200;

    float p[16];
    #pragma unroll
    for (int i = 0; i < 16; i++) p[i] = 0.f;
    #pragma unroll 1
    for (int j = lane; j < 200; j += 32) {
        int ch = j / 25;
        float fv = fmaf(src[j], sc[ch], shh[ch]);
        #pragma unroll
        for (int i = 0; i < 16; i++) p[i] = fmaf(sW1[i * 200 + j], fv, p[i]);
    }
    #pragma unroll
    for (int i = 0; i < 16; i++) {
        #pragma unroll
        for (int off = 16; off > 0; off >>= 1)
            p[i] += __shfl_xor_sync(0xffffffffu, p[i], off);
        p[i] = fmaxf(p[i] + sb1[i], 0.f);
    }
    // fc2: lane computes output index 'lane'
    float a = sb2[lane];
    #pragma unroll
    for (int j = 0; j < 16; j++) a = fmaf(sW2[lane * 16 + j], p[j], a);
    float f2 = fmaxf(a, 0.f);
    // heads: 5 dot products across 32 lanes
    float v0 = sWz[lane]      * f2;
    float v1 = sWz[32 + lane] * f2;
    float v2 = sWL[lane]      * f2;
    float v3 = sWL[32 + lane] * f2;
    float v4 = sWL[64 + lane] * f2;
    #pragma unroll
    for (int off = 16; off > 0; off >>= 1) {
        v0 += __shfl_xor_sync(0xffffffffu, v0, off);
        v1 += __shfl_xor_sync(0xffffffffu, v1, off);
        v2 += __shfl_xor_sync(0xffffffffu, v2, off);
        v3 += __shfl_xor_sync(0xffffffffu, v3, off);
        v4 += __shfl_xor_sync(0xffffffffu, v4, off);
    }
    if (lane == 0) {
        g_z[n * 2]     = v0 + sbz[0];
        g_z[n * 2 + 1] = v1 + sbz[1];
        g_L[n * 3]     = v2 + sbL[0];
        g_L[n * 3 + 1] = v3 + sbL[1];
        g_L[n * 3 + 2] = v4 + sbL[2];
    }
}

// ---------------- Kalman filter: one lane per sequence ----------------
__global__ void k_kf(const float* __restrict__ Ag, const float* __restrict__ Bg,
                     const float* __restrict__ Cg, const float* __restrict__ Qg,
                     float* __restrict__ out)
{
    const int b = threadIdx.x;
    if (b >= 8) return;
    float A[16], C[8], BQBT[16], Bm[8], Q[4];
    #pragma unroll
    for (int i = 0; i < 16; i++) A[i] = Ag[i];
    #pragma unroll
    for (int i = 0; i < 8; i++)  C[i] = Cg[i];
    #pragma unroll
    for (int i = 0; i < 8; i++)  Bm[i] = Bg[i];
    #pragma unroll
    for (int i = 0; i < 4; i++)  Q[i] = Qg[i];
    #pragma unroll
    for (int i = 0; i < 4; i++) {
        float bq0 = Bm[i * 2] * Q[0] + Bm[i * 2 + 1] * Q[2];
        float bq1 = Bm[i * 2] * Q[1] + Bm[i * 2 + 1] * Q[3];
        #pragma unroll
        for (int l = 0; l < 4; l++)
            BQBT[i * 4 + l] = bq0 * Bm[l * 2] + bq1 * Bm[l * 2 + 1];
    }
    const float* zp = g_z + b * 200;
    const float* Lp = g_L + b * 300;
    float h[4] = {zp[0], zp[1], 0.f, 0.f};
    float l0 = Lp[0], l1 = Lp[1], l2 = Lp[2];
    float s[16] = {l0 * l0, l0 * l1, 0.f, 0.f,
                   l0 * l1, l1 * l1 + l2 * l2, 0.f, 0.f,
                   0.f, 0.f, 1.f, 0.f,
                   0.f, 0.f, 0.f, 1.f};
    float* ob = out + b * 400;
    ob[0] = h[0]; ob[1] = h[1]; ob[2] = h[2]; ob[3] = h[3];

    for (int t = 1; t < 100; t++) {
        float zx = zp[t * 2], zy = zp[t * 2 + 1];
        float La = Lp[t * 3], Lb = Lp[t * 3 + 1], Lc = Lp[t * 3 + 2];
        float r00 = La * La, r01 = La * Lb, r11 = Lb * Lb + Lc * Lc;
        float hp[4];
        #pragma unroll
        for (int i = 0; i < 4; i++)
            hp[i] = A[i*4]*h[0] + A[i*4+1]*h[1] + A[i*4+2]*h[2] + A[i*4+3]*h[3];
        float tmp[16];
        #pragma unroll
        for (int i = 0; i < 4; i++)
            #pragma unroll
            for (int k = 0; k < 4; k++)
                tmp[i*4+k] = A[i*4]*s[k] + A[i*4+1]*s[4+k] + A[i*4+2]*s[8+k] + A[i*4+3]*s[12+k];
        float sp[16];
        #pragma unroll
        for (int i = 0; i < 4; i++)
            #pragma unroll
            for (int l = 0; l < 4; l++)
                sp[i*4+l] = BQBT[i*4+l] + tmp[i*4]*A[l*4] + tmp[i*4+1]*A[l*4+1]
                          + tmp[i*4+2]*A[l*4+2] + tmp[i*4+3]*A[l*4+3];
        float sct[8];  // sp @ C^T
        #pragma unroll
        for (int i = 0; i < 4; i++)
            #pragma unroll
            for (int j = 0; j < 2; j++)
                sct[i*2+j] = sp[i*4]*C[j*4] + sp[i*4+1]*C[j*4+1]
                           + sp[i*4+2]*C[j*4+2] + sp[i*4+3]*C[j*4+3];
        float S00 = C[0]*sct[0] + C[1]*sct[2] + C[2]*sct[4] + C[3]*sct[6] + r00;
        float S01 = C[0]*sct[1] + C[1]*sct[3] + C[2]*sct[5] + C[3]*sct[7] + r01;
        float S10 = C[4]*sct[0] + C[5]*sct[2] + C[6]*sct[4] + C[7]*sct[6] + r01;
        float S11 = C[4]*sct[1] + C[5]*sct[3] + C[6]*sct[5] + C[7]*sct[7] + r11;
        float idet = 1.f / (S00 * S11 - S01 * S10);
        float Si00 = S11 * idet, Si01 = -S01 * idet, Si10 = -S10 * idet, Si11 = S00 * idet;
        float K[8];
        #pragma unroll
        for (int i = 0; i < 4; i++) {
            K[i*2]   = sct[i*2]*Si00 + sct[i*2+1]*Si10;
            K[i*2+1] = sct[i*2]*Si01 + sct[i*2+1]*Si11;
        }
        float a0 = zx - (C[0]*hp[0] + C[1]*hp[1] + C[2]*hp[2] + C[3]*hp[3]);
        float a1 = zy - (C[4]*hp[0] + C[5]*hp[1] + C[6]*hp[2] + C[7]*hp[3]);
        #pragma unroll
        for (int i = 0; i < 4; i++) h[i] = hp[i] + K[i*2]*a0 + K[i*2+1]*a1;
        float M[16];
        #pragma unroll
        for (int i = 0; i < 4; i++)
            #pragma unroll
            for (int j = 0; j < 4; j++)
                M[i*4+j] = (i == j ? 1.f : 0.f) - (K[i*2]*C[j] + K[i*2+1]*C[4+j]);
        #pragma unroll
        for (int i = 0; i < 4; i++)
            #pragma unroll
            for (int l = 0; l < 4; l++)
                s[i*4+l] = M[i*4]*sp[l] + M[i*4+1]*sp[4+l]
                         + M[i*4+2]*sp[8+l] + M[i*4+3]*sp[12+l];
        ob[t*4]   = h[0]; ob[t*4+1] = h[1];
        ob[t*4+2] = h[2]; ob[t*4+3] = h[3];
    }
}

extern "C" void kernel_launch(void* const* d_in, const int* in_sizes, int n_in,
                              void* d_out, int out_size) {
    const float* x    = (const float*)d_in[0];
    const float* c1w  = (const float*)d_in[1];
    const float* c1b  = (const float*)d_in[2];
    const float* bn1g = (const float*)d_in[3];
    const float* bn1b = (const float*)d_in[4];
    const float* c2w  = (const float*)d_in[5];
    const float* c2b  = (const float*)d_in[6];
    const float* bn2g = (const float*)d_in[7];
    const float* bn2b = (const float*)d_in[8];
    const float* W1   = (const float*)d_in[9];
    const float* b1   = (const float*)d_in[10];
    const float* W2   = (const float*)d_in[11];
    const float* b2   = (const float*)d_in[12];
    const float* Wz   = (const float*)d_in[13];
    const float* bz   = (const float*)d_in[14];
    const float* WL   = (const float*)d_in[15];
    const float* bL   = (const float*)d_in[16];
    const float* A    = (const float*)d_in[17];
    const float* B    = (const float*)d_in[18];
    const float* C    = (const float*)d_in[19];
    const float* Q    = (const float*)d_in[20];
    float* out = (float*)d_out;

    k_zero<<<1, 32>>>();
    k_pad1<<<1, 32>>>();
    k_pad2<<<1, 32>>>();
    k_conv1<<<dim3(6, 800), 160>>>(x, c1w, c1b);
    k_conv2<<<800, 224>>>(c2w, c2b, bn1g, bn1b);
    k_fc<<<100, 256>>>(W1, b1, W2, b2, Wz, bz, WL, bL, bn2g, bn2b);
    k_kf<<<1, 32>>>(A, B, C, Q, out);
}

// round 3
// speedup vs baseline: 2.2701x; 1.3492x over previous
#include <cuda_runtime.h>

#define NIMG 800

// ---------------- scratch (no allocation allowed) ----------------
__device__ float  g_buf1[NIMG * 4 * 30 * 30];   // conv1 pooled output (NCHW)
__device__ float  g_buf2[NIMG * 8 * 25];        // conv2 pooled output (NCHW)
__device__ float  g_z[NIMG * 2];
__device__ float  g_L[NIMG * 3];
__device__ double g_stats[24];  // [0:4) bn1 sum, [4:8) bn1 sumsq, [8:16) bn2 sum, [16:24) bn2 sumsq
__device__ int    g_sink;

__global__ void k_zero() { if (threadIdx.x < 24) g_stats[threadIdx.x] = 0.0; }
__global__ void k_pad1() { if (threadIdx.x == 0) g_sink = 1; }
__global__ void k_pad2() { if (threadIdx.x == 0) g_sink = 2; }

// ---- f32x2 packed-math helpers (Blackwell; ptxas never auto-fuses these) ----
__device__ __forceinline__ unsigned long long ffma2(unsigned long long a,
                                                    unsigned long long b,
                                                    unsigned long long c) {
    unsigned long long d;
    asm("fma.rn.f32x2 %0, %1, %2, %3;" : "=l"(d) : "l"(a), "l"(b), "l"(c));
    return d;
}
__device__ __forceinline__ unsigned long long packbc(float x) {  // (x, x)
    unsigned long long d;
    asm("mov.b64 %0, {%1, %2};" : "=l"(d) : "f"(x), "f"(x));
    return d;
}
__device__ __forceinline__ void unpack2(unsigned long long v, float& lo, float& hi) {
    asm("mov.b64 {%0, %1}, %2;" : "=f"(lo), "=f"(hi) : "l"(v));
}

// ---------------- conv1 + bias + relu + maxpool2 + bn1-stats ----------------
// input x: (N,128,128,3) NHWC. conv 9x9 stride 2 -> 60x60, pool -> 30x30.
// Block: one image, 5 pooled rows. Thread: one pooled pixel, all 4 oc (FFMA2 oc-pairs).
__global__ __launch_bounds__(160) void k_conv1(
    const float* __restrict__ x, const float* __restrict__ cw,
    const float* __restrict__ cb)
{
    __shared__ __align__(16) float sm_in[3 * 3460];  // planar [3][27][128], plane stride 3460
    __shared__ __align__(16) float sm_w[972];        // [ic][kh][kw][oc] (oc pairs adjacent)
    __shared__ float sm_b[4];
    __shared__ float s_part[5][8];
    const int tid = threadIdx.x;
    const int n   = blockIdx.y;
    const int r0  = blockIdx.x * 5;

    if (tid < 4) sm_b[tid] = cb[tid];
    // weights: global OIHW (4,3,9,9) -> smem [((ic*9+kh)*9+kw)*4 + oc]
    for (int i = tid; i < 972; i += 160) {
        int oc = i & 3; int rest = i >> 2;
        int kw = rest % 9; int t2 = rest / 9; int kh = t2 % 9; int ic = t2 / 9;
        sm_w[i] = cw[oc * 243 + ic * 81 + kh * 9 + kw];
    }
    // de-interleave NHWC -> planar in 12-float groups: 3x LDG.128 -> 3x STS.128
    const float4* xb = (const float4*)(x + (size_t)n * 49152 + (size_t)r0 * 1536);
    for (int i = tid; i < 864; i += 160) {            // 27 rows x 32 groups
        int row = i >> 5; int g = i & 31;
        const float4* src = xb + row * 96 + g * 3;
        float4 a = src[0], b = src[1], c = src[2];
        int base = row * 128 + 4 * g;
        *(float4*)(sm_in + base)            = make_float4(a.x, a.w, b.z, c.y);
        *(float4*)(sm_in + 3460 + base)     = make_float4(a.y, b.x, b.w, c.z);
        *(float4*)(sm_in + 6920 + base)     = make_float4(a.z, b.y, c.x, c.w);
    }
    __syncthreads();

    const bool valid = (tid < 150);
    const int pw  = tid % 30;
    const int phl = valid ? (tid / 30) : 4;

    // acc[p][dy][dx]: p=0 -> (oc0,oc1), p=1 -> (oc2,oc3)
    unsigned long long acc[2][2][2];
    #pragma unroll
    for (int p = 0; p < 2; p++)
        #pragma unroll
        for (int dy = 0; dy < 2; dy++) { acc[p][dy][0] = 0ull; acc[p][dy][1] = 0ull; }

    #pragma unroll 1
    for (int ic = 0; ic < 3; ic++) {
        const float* pl = sm_in + ic * 3460 + phl * 512 + pw * 4;
        const float* wb = sm_w + ic * 324;
        #pragma unroll 1
        for (int kh = 0; kh < 9; kh++) {
            // row for dy=0 (r=kh) and dy=1 (r=kh+2); broadcast packs
            unsigned long long bpa[11], bpb[11];
            {
                const float* rp = pl + kh * 128;
                float4 va = *(const float4*)(rp);
                float4 vb = *(const float4*)(rp + 4);
                float4 vc = *(const float4*)(rp + 8);
                float in[12] = {va.x, va.y, va.z, va.w, vb.x, vb.y, vb.z, vb.w,
                                vc.x, vc.y, vc.z, vc.w};
                #pragma unroll
                for (int j = 0; j < 11; j++) bpa[j] = packbc(in[j]);
            }
            {
                const float* rp = pl + (kh + 2) * 128;
                float4 va = *(const float4*)(rp);
                float4 vb = *(const float4*)(rp + 4);
                float4 vc = *(const float4*)(rp + 8);
                float in[12] = {va.x, va.y, va.z, va.w, vb.x, vb.y, vb.z, vb.w,
                                vc.x, vc.y, vc.z, vc.w};
                #pragma unroll
                for (int j = 0; j < 11; j++) bpb[j] = packbc(in[j]);
            }
            #pragma unroll
            for (int kw = 0; kw < 9; kw++) {
                ulonglong2 w2 = *(const ulonglong2*)(wb + (kh * 9 + kw) * 4);
                acc[0][0][0] = ffma2(w2.x, bpa[kw],     acc[0][0][0]);
                acc[0][0][1] = ffma2(w2.x, bpa[kw + 2], acc[0][0][1]);
                acc[1][0][0] = ffma2(w2.y, bpa[kw],     acc[1][0][0]);
                acc[1][0][1] = ffma2(w2.y, bpa[kw + 2], acc[1][0][1]);
                acc[0][1][0] = ffma2(w2.x, bpb[kw],     acc[0][1][0]);
                acc[0][1][1] = ffma2(w2.x, bpb[kw + 2], acc[0][1][1]);
                acc[1][1][0] = ffma2(w2.y, bpb[kw],     acc[1][1][0]);
                acc[1][1][1] = ffma2(w2.y, bpb[kw + 2], acc[1][1][1]);
            }
        }
    }
    // unpack, pool(max), bias, relu
    float m4[4];
    #pragma unroll
    for (int p = 0; p < 2; p++) {
        float l00, h00, l01, h01, l10, h10, l11, h11;
        unpack2(acc[p][0][0], l00, h00);
        unpack2(acc[p][0][1], l01, h01);
        unpack2(acc[p][1][0], l10, h10);
        unpack2(acc[p][1][1], l11, h11);
        m4[2 * p]     = fmaxf(fmaxf(l00, l01), fmaxf(l10, l11));
        m4[2 * p + 1] = fmaxf(fmaxf(h00, h01), fmaxf(h10, h11));
    }
    const int ph = r0 + phl;
    float vs[4], vq[4];
    #pragma unroll
    for (int oc = 0; oc < 4; oc++) {
        float m = fmaxf(m4[oc] + sm_b[oc], 0.f);
        if (valid) g_buf1[((n * 4 + oc) * 30 + ph) * 30 + pw] = m;
        vs[oc] = valid ? m : 0.f;
        vq[oc] = valid ? m * m : 0.f;
    }
    #pragma unroll
    for (int oc = 0; oc < 4; oc++)
        #pragma unroll
        for (int off = 16; off > 0; off >>= 1) {
            vs[oc] += __shfl_xor_sync(0xffffffffu, vs[oc], off);
            vq[oc] += __shfl_xor_sync(0xffffffffu, vq[oc], off);
        }
    const int wp = tid >> 5;
    if ((tid & 31) == 0) {
        #pragma unroll
        for (int oc = 0; oc < 4; oc++) {
            s_part[wp][oc]     = vs[oc];
            s_part[wp][4 + oc] = vq[oc];
        }
    }
    __syncthreads();
    if (tid < 8) {
        float t = 0.f;
        #pragma unroll
        for (int w = 0; w < 5; w++) t += s_part[w][tid];
        atomicAdd(&g_stats[tid], (double)t);
    }
}

// ---------------- bn1-apply + conv2 + relu + pool + bn2-stats ----------------
__global__ __launch_bounds__(224) void k_conv2(
    const float* __restrict__ cw, const float* __restrict__ cb,
    const float* __restrict__ g1, const float* __restrict__ b1)
{
    __shared__ __align__(16) float sm_in[4 * 960];
    __shared__ float sm_w[2592];
    __shared__ float sm_b[8];
    __shared__ float sc[4], shh[4];
    __shared__ float s_sum[8], s_sq[8];
    const int tid = threadIdx.x;
    const int n   = blockIdx.x;
    if (tid < 4) {
        double mu  = g_stats[tid] * (1.0 / 720000.0);
        double var = g_stats[4 + tid] * (1.0 / 720000.0) - mu * mu;
        float scale = g1[tid] * rsqrtf((float)var + 1e-5f);
        sc[tid] = scale; shh[tid] = b1[tid] - (float)mu * scale;
    }
    if (tid < 8) { s_sum[tid] = 0.f; s_sq[tid] = 0.f; sm_b[tid] = cb[tid]; }
    __syncthreads();
    for (int i = tid; i < 3600; i += 224) {
        int ic = i / 900; int rem = i - ic * 900;
        int row = rem / 30; int col = rem - row * 30;
        int chunk = col >> 2, within = col & 3;
        int pcol = (((chunk ^ (row & 7)) << 2) | within);
        sm_in[ic * 960 + row * 32 + pcol] = fmaf(g_buf1[n * 3600 + i], sc[ic], shh[ic]);
    }
    for (int i = tid; i < 2592; i += 224) sm_w[i] = cw[i];
    __syncthreads();
    if (tid < 200) {
        const int oc = tid / 25;
        const int p  = tid - oc * 25;
        const int pr = p / 5, pc = p - pr * 5;
        float acc[2][2] = {{0.f, 0.f}, {0.f, 0.f}};
        #pragma unroll 1
        for (int ic = 0; ic < 4; ic++) {
            const float* wb = sm_w + oc * 324 + ic * 81;
            const float* ib = sm_in + ic * 960;
            #pragma unroll 1
            for (int kh = 0; kh < 9; kh++) {
                float w[9];
                #pragma unroll
                for (int kw = 0; kw < 9; kw++) w[kw] = wb[kh * 9 + kw];
                #pragma unroll
                for (int dy = 0; dy < 2; dy++) {
                    const int row = 4 * pr + 2 * dy + kh;
                    const int rb  = row * 32;
                    const int rx  = row & 7;
                    float4 v0 = *(const float4*)(ib + rb + (((pc    ) ^ rx) << 2));
                    float4 v1 = *(const float4*)(ib + rb + (((pc + 1) ^ rx) << 2));
                    float4 v2 = *(const float4*)(ib + rb + (((pc + 2) ^ rx) << 2));
                    float in[12] = {v0.x, v0.y, v0.z, v0.w, v1.x, v1.y, v1.z, v1.w,
                                    v2.x, v2.y, v2.z, v2.w};
                    #pragma unroll
                    for (int kw = 0; kw < 9; kw++) {
                        acc[dy][0] = fmaf(w[kw], in[kw],     acc[dy][0]);
                        acc[dy][1] = fmaf(w[kw], in[kw + 2], acc[dy][1]);
                    }
                }
            }
        }
        float b = sm_b[oc];
        float m = fmaxf(fmaxf(acc[0][0], acc[0][1]), fmaxf(acc[1][0], acc[1][1]));
        m = fmaxf(m + b, 0.f);
        g_buf2[(n * 8 + oc) * 25 + p] = m;
        atomicAdd(&s_sum[oc], m);
        atomicAdd(&s_sq[oc], m * m);
    }
    __syncthreads();
    if (tid < 8) {
        atomicAdd(&g_stats[8 + tid],  (double)s_sum[tid]);
        atomicAdd(&g_stats[16 + tid], (double)s_sq[tid]);
    }
}

// ---------------- bn2-apply + fc1(relu) + fc2(relu) + fc3z / fc3L ----------------
__global__ __launch_bounds__(256) void k_fc(
    const float* __restrict__ W1, const float* __restrict__ b1,
    const float* __restrict__ W2, const float* __restrict__ b2,
    const float* __restrict__ Wz, const float* __restrict__ bz,
    const float* __restrict__ WL, const float* __restrict__ bL,
    const float* __restrict__ g2, const float* __restrict__ be2)
{
    __shared__ float sW1[3200], sW2[512], sWz[64], sWL[96];
    __shared__ float sb1[16], sb2[32], sbz[2], sbL[3];
    __shared__ float sc[8], shh[8];
    const int tid = threadIdx.x;
    if (tid < 8) {
        double mu  = g_stats[8 + tid] * (1.0 / 20000.0);
        double var = g_stats[16 + tid] * (1.0 / 20000.0) - mu * mu;
        float scale = g2[tid] * rsqrtf((float)var + 1e-5f);
        sc[tid] = scale; shh[tid] = be2[tid] - (float)mu * scale;
    }
    for (int i = tid; i < 3200; i += 256) sW1[i] = W1[i];
    for (int i = tid; i < 512;  i += 256) sW2[i] = W2[i];
    if (tid < 64) sWz[tid] = Wz[tid];
    if (tid < 96) sWL[tid] = WL[tid];
    if (tid < 16) sb1[tid] = b1[tid];
    if (tid < 32) sb2[tid] = b2[tid];
    if (tid < 2)  sbz[tid] = bz[tid];
    if (tid < 3)  sbL[tid] = bL[tid];
    __syncthreads();

    const int lane = tid & 31;
    const int n = blockIdx.x * 8 + (tid >> 5);
    const float* src = g_buf2 + n * 200;

    float p[16];
    #pragma unroll
    for (int i = 0; i < 16; i++) p[i] = 0.f;
    #pragma unroll 1
    for (int j = lane; j < 200; j += 32) {
        int ch = j / 25;
        float fv = fmaf(src[j], sc[ch], shh[ch]);
        #pragma unroll
        for (int i = 0; i < 16; i++) p[i] = fmaf(sW1[i * 200 + j], fv, p[i]);
    }
    #pragma unroll
    for (int i = 0; i < 16; i++) {
        #pragma unroll
        for (int off = 16; off > 0; off >>= 1)
            p[i] += __shfl_xor_sync(0xffffffffu, p[i], off);
        p[i] = fmaxf(p[i] + sb1[i], 0.f);
    }
    float a = sb2[lane];
    #pragma unroll
    for (int j = 0; j < 16; j++) a = fmaf(sW2[lane * 16 + j], p[j], a);
    float f2 = fmaxf(a, 0.f);
    float v0 = sWz[lane]      * f2;
    float v1 = sWz[32 + lane] * f2;
    float v2 = sWL[lane]      * f2;
    float v3 = sWL[32 + lane] * f2;
    float v4 = sWL[64 + lane] * f2;
    #pragma unroll
    for (int off = 16; off > 0; off >>= 1) {
        v0 += __shfl_xor_sync(0xffffffffu, v0, off);
        v1 += __shfl_xor_sync(0xffffffffu, v1, off);
        v2 += __shfl_xor_sync(0xffffffffu, v2, off);
        v3 += __shfl_xor_sync(0xffffffffu, v3, off);
        v4 += __shfl_xor_sync(0xffffffffu, v4, off);
    }
    if (lane == 0) {
        g_z[n * 2]     = v0 + sbz[0];
        g_z[n * 2 + 1] = v1 + sbz[1];
        g_L[n * 3]     = v2 + sbL[0];
        g_L[n * 3 + 1] = v3 + sbL[1];
        g_L[n * 3 + 2] = v4 + sbL[2];
    }
}

// ---------------- Kalman filter: one lane per sequence ----------------
__global__ void k_kf(const float* __restrict__ Ag, const float* __restrict__ Bg,
                     const float* __restrict__ Cg, const float* __restrict__ Qg,
                     float* __restrict__ out)
{
    const int b = threadIdx.x;
    if (b >= 8) return;
    float A[16], C[8], BQBT[16], Bm[8], Q[4];
    #pragma unroll
    for (int i = 0; i < 16; i++) A[i] = Ag[i];
    #pragma unroll
    for (int i = 0; i < 8; i++)  C[i] = Cg[i];
    #pragma unroll
    for (int i = 0; i < 8; i++)  Bm[i] = Bg[i];
    #pragma unroll
    for (int i = 0; i < 4; i++)  Q[i] = Qg[i];
    #pragma unroll
    for (int i = 0; i < 4; i++) {
        float bq0 = Bm[i * 2] * Q[0] + Bm[i * 2 + 1] * Q[2];
        float bq1 = Bm[i * 2] * Q[1] + Bm[i * 2 + 1] * Q[3];
        #pragma unroll
        for (int l = 0; l < 4; l++)
            BQBT[i * 4 + l] = bq0 * Bm[l * 2] + bq1 * Bm[l * 2 + 1];
    }
    // C == [I2 | 0] structural fast path (verified at runtime)
    const bool cI = (C[0] == 1.f && C[1] == 0.f && C[2] == 0.f && C[3] == 0.f &&
                     C[4] == 0.f && C[5] == 1.f && C[6] == 0.f && C[7] == 0.f);
    const float* zp = g_z + b * 200;
    const float* Lp = g_L + b * 300;
    float h[4] = {zp[0], zp[1], 0.f, 0.f};
    float l0 = Lp[0], l1 = Lp[1], l2 = Lp[2];
    float s[16] = {l0 * l0, l0 * l1, 0.f, 0.f,
                   l0 * l1, l1 * l1 + l2 * l2, 0.f, 0.f,
                   0.f, 0.f, 1.f, 0.f,
                   0.f, 0.f, 0.f, 1.f};
    float* ob = out + b * 400;
    ob[0] = h[0]; ob[1] = h[1]; ob[2] = h[2]; ob[3] = h[3];

    for (int t = 1; t < 100; t++) {
        float zx = zp[t * 2], zy = zp[t * 2 + 1];
        float La = Lp[t * 3], Lb = Lp[t * 3 + 1], Lc = Lp[t * 3 + 2];
        float r00 = La * La, r01 = La * Lb, r11 = Lb * Lb + Lc * Lc;
        float hp[4];
        #pragma unroll
        for (int i = 0; i < 4; i++)
            hp[i] = A[i*4]*h[0] + A[i*4+1]*h[1] + A[i*4+2]*h[2] + A[i*4+3]*h[3];
        float tmp[16];
        #pragma unroll
        for (int i = 0; i < 4; i++)
            #pragma unroll
            for (int k = 0; k < 4; k++)
                tmp[i*4+k] = A[i*4]*s[k] + A[i*4+1]*s[4+k] + A[i*4+2]*s[8+k] + A[i*4+3]*s[12+k];
        float sp[16];
        #pragma unroll
        for (int i = 0; i < 4; i++)
            #pragma unroll
            for (int l = 0; l < 4; l++)
                sp[i*4+l] = BQBT[i*4+l] + tmp[i*4]*A[l*4] + tmp[i*4+1]*A[l*4+1]
                          + tmp[i*4+2]*A[l*4+2] + tmp[i*4+3]*A[l*4+3];
        if (cI) {
            float S00 = sp[0] + r00, S01 = sp[1] + r01;
            float S10 = sp[4] + r01, S11 = sp[5] + r11;
            float idet = 1.f / (S00 * S11 - S01 * S10);
            float Si00 = S11 * idet, Si01 = -S01 * idet;
            float Si10 = -S10 * idet, Si11 = S00 * idet;
            float K[8];
            #pragma unroll
            for (int i = 0; i < 4; i++) {
                K[i*2]   = sp[i*4]*Si00 + sp[i*4+1]*Si10;
                K[i*2+1] = sp[i*4]*Si01 + sp[i*4+1]*Si11;
            }
            float a0 = zx - hp[0];
            float a1 = zy - hp[1];
            #pragma unroll
            for (int i = 0; i < 4; i++) h[i] = hp[i] + K[i*2]*a0 + K[i*2+1]*a1;
            #pragma unroll
            for (int i = 0; i < 4; i++)
                #pragma unroll
                for (int l = 0; l < 4; l++)
                    s[i*4+l] = sp[i*4+l] - K[i*2]*sp[l] - K[i*2+1]*sp[4+l];
        } else {
            float sct[8];
            #pragma unroll
            for (int i = 0; i < 4; i++)
                #pragma unroll
                for (int j = 0; j < 2; j++)
                    sct[i*2+j] = sp[i*4]*C[j*4] + sp[i*4+1]*C[j*4+1]
                               + sp[i*4+2]*C[j*4+2] + sp[i*4+3]*C[j*4+3];
            float S00 = C[0]*sct[0] + C[1]*sct[2] + C[2]*sct[4] + C[3]*sct[6] + r00;
            float S01 = C[0]*sct[1] + C[1]*sct[3] + C[2]*sct[5] + C[3]*sct[7] + r01;
            float S10 = C[4]*sct[0] + C[5]*sct[2] + C[6]*sct[4] + C[7]*sct[6] + r01;
            float S11 = C[4]*sct[1] + C[5]*sct[3] + C[6]*sct[5] + C[7]*sct[7] + r11;
            float idet = 1.f / (S00 * S11 - S01 * S10);
            float Si00 = S11 * idet, Si01 = -S01 * idet, Si10 = -S10 * idet, Si11 = S00 * idet;
            float K[8];
            #pragma unroll
            for (int i = 0; i < 4; i++) {
                K[i*2]   = sct[i*2]*Si00 + sct[i*2+1]*Si10;
                K[i*2+1] = sct[i*2]*Si01 + sct[i*2+1]*Si11;
            }
            float a0 = zx - (C[0]*hp[0] + C[1]*hp[1] + C[2]*hp[2] + C[3]*hp[3]);
            float a1 = zy - (C[4]*hp[0] + C[5]*hp[1] + C[6]*hp[2] + C[7]*hp[3]);
            #pragma unroll
            for (int i = 0; i < 4; i++) h[i] = hp[i] + K[i*2]*a0 + K[i*2+1]*a1;
            float M[16];
            #pragma unroll
            for (int i = 0; i < 4; i++)
                #pragma unroll
                for (int j = 0; j < 4; j++)
                    M[i*4+j] = (i == j ? 1.f : 0.f) - (K[i*2]*C[j] + K[i*2+1]*C[4+j]);
            #pragma unroll
            for (int i = 0; i < 4; i++)
                #pragma unroll
                for (int l = 0; l < 4; l++)
                    s[i*4+l] = M[i*4]*sp[l] + M[i*4+1]*sp[4+l]
                             + M[i*4+2]*sp[8+l] + M[i*4+3]*sp[12+l];
        }
        ob[t*4]   = h[0]; ob[t*4+1] = h[1];
        ob[t*4+2] = h[2]; ob[t*4+3] = h[3];
    }
}

extern "C" void kernel_launch(void* const* d_in, const int* in_sizes, int n_in,
                              void* d_out, int out_size) {
    const float* x    = (const float*)d_in[0];
    const float* c1w  = (const float*)d_in[1];
    const float* c1b  = (const float*)d_in[2];
    const float* bn1g = (const float*)d_in[3];
    const float* bn1b = (const float*)d_in[4];
    const float* c2w  = (const float*)d_in[5];
    const float* c2b  = (const float*)d_in[6];
    const float* bn2g = (const float*)d_in[7];
    const float* bn2b = (const float*)d_in[8];
    const float* W1   = (const float*)d_in[9];
    const float* b1   = (const float*)d_in[10];
    const float* W2   = (const float*)d_in[11];
    const float* b2   = (const float*)d_in[12];
    const float* Wz   = (const float*)d_in[13];
    const float* bz   = (const float*)d_in[14];
    const float* WL   = (const float*)d_in[15];
    const float* bL   = (const float*)d_in[16];
    const float* A    = (const float*)d_in[17];
    const float* B    = (const float*)d_in[18];
    const float* C    = (const float*)d_in[19];
    const float* Q    = (const float*)d_in[20];
    float* out = (float*)d_out;

    k_zero<<<1, 32>>>();
    k_pad1<<<1, 32>>>();
    k_pad2<<<1, 32>>>();
    k_conv1<<<dim3(6, 800), 160>>>(x, c1w, c1b);
    k_conv2<<<800, 224>>>(c2w, c2b, bn1g, bn1b);
    k_fc<<<100, 256>>>(W1, b1, W2, b2, Wz, bz, WL, bL, bn2g, bn2b);
    k_kf<<<1, 32>>>(A, B, C, Q, out);
}